// round 15
// baseline (speedup 1.0000x reference)
#include <cuda_runtime.h>
#include <cuda_fp16.h>
#include <cstdint>
#include <cstddef>

// ---------------------------------------------------------------------------
// Dipole head: asymmetric fp16 GEMMs on mma.sync (HMMA), fp32 accum.
// R15: cp.async issue-rate is the bottleneck (4096 ops/chunk = 2x HMMA time).
//      K=256 GEMMs (1,3,4) -> persistent-B kernel: B (128KB) loaded once per
//      CTA, CTA loops M-tiles with an A-only 2-stage ring. ~48% fewer LSU ops.
//      GEMM2 (K=512) keeps the streaming path.
// Per-accumulator math order unchanged -> rel_err stays ~7.16e-4.
// ---------------------------------------------------------------------------

#define NA_MAX 200000
#define MPAD   200128

// ---------------- global scratch ----------------
__device__ __align__(128) float g_vw[(size_t)3 * NA_MAX * 256];   // vW fp32
__device__ __align__(128) __half g_a2h[(size_t)MPAD * 512];
__device__ __align__(128) __half g_a2l[(size_t)MPAD * 512];
__device__ __align__(128) __half g_a3h[(size_t)MPAD * 256];
__device__ __align__(128) __half g_a3l[(size_t)MPAD * 256];
__device__ __align__(128) __half g_a4h[(size_t)MPAD * 256];
__device__ __align__(128) __half g_a4l[(size_t)MPAD * 256];
__device__ float g_vvn2[NA_MAX];
__device__ float g_vw2[3 * NA_MAX];
__device__ __align__(128) __half g_bt1[512 * 256];
__device__ __align__(128) __half g_bt2[256 * 512];
__device__ __align__(128) __half g_bt3[512 * 256];
__device__ __align__(128) __half g_bt4[256 * 256];

// ---------------- helpers ----------------------------------------------
__device__ __forceinline__ uint32_t smem_u32(const void* p) {
    uint32_t a;
    asm("{ .reg .u64 t; cvta.to.shared.u64 t, %1; cvt.u32.u64 %0, t; }"
        : "=r"(a) : "l"(p));
    return a;
}
#define SWZ128(off) ((off) ^ (((off) >> 3) & 0x70))

__device__ __forceinline__ void cp16(uint32_t saddr, const void* gaddr) {
    asm volatile("cp.async.cg.shared.global [%0], [%1], 16;\n"
                 :: "r"(saddr), "l"(gaddr));
}
__device__ __forceinline__ void cp_commit() {
    asm volatile("cp.async.commit_group;\n" ::: "memory");
}

__device__ __forceinline__ void ldsm_x4(uint32_t* r, uint32_t a) {
    asm volatile("ldmatrix.sync.aligned.m8n8.x4.shared.b16 {%0,%1,%2,%3}, [%4];"
                 : "=r"(r[0]), "=r"(r[1]), "=r"(r[2]), "=r"(r[3]) : "r"(a));
}

__device__ __forceinline__ void mma16816(float* d, const uint32_t* a,
                                         const uint32_t* b) {
    asm volatile(
        "mma.sync.aligned.m16n8k16.row.col.f32.f16.f16.f32 "
        "{%0,%1,%2,%3}, {%4,%5,%6,%7}, {%8,%9}, {%0,%1,%2,%3};\n"
        : "+f"(d[0]), "+f"(d[1]), "+f"(d[2]), "+f"(d[3])
        : "r"(a[0]), "r"(a[1]), "r"(a[2]), "r"(a[3]), "r"(b[0]), "r"(b[1]));
}

__device__ __forceinline__ float silu_f(float x) { return x / (1.0f + __expf(-x)); }

__device__ __forceinline__ void split_f16(float v, __half& h, __half& l) {
    h = __float2half_rn(v);
    l = __float2half_rn(v - __half2float(h));
}

// ---------------------------------------------------------------------------
struct MP {
    const float*  Af;        // fp32 A source (GEMM1/2 first half)
    int           ldaf;
    const __half *Ah, *Al;   // fp16 A source
    int           ldah, coffh;
    const __half *B;
    int M, K, ksplit, mstep;
    int tpc, ntiles;         // persistent-B: tiles per CTA, total M-tiles
    float *C0;
    __half *Oh, *Ol;
    const float *bias, *u, *vrow;
    const float *vw, *Wmix2;
    float *vvn2, *vw2;
    const float *W2b, *b2b, *pos;
    const int *batch;
    float *out;
    int nmol;
};

#define SROW 264

// ===========================================================================
// Persistent-B kernel for K=256 GEMMs (EPI 0 = GEMM1, 2 = GEMM3, 3 = GEMM4).
// smem: [0,128K) B (4 chunk-tiles x 32KB), [128K,192K) A ring 2 x 32KB.
// ===========================================================================
#define PB_STG   131072u
#define PB_STGSZ 32768u
#define SMEM_P   196608

template <int EPI>
__global__ void __launch_bounds__(512, 1) gemm_persb(const MP p) {
    extern __shared__ __align__(1024) char smem[];
    const uint32_t sb = smem_u32(smem);
    const int tid  = threadIdx.x;
    const int wid  = tid >> 5;
    const int lane = tid & 31;
    const int wm   = wid >> 2;
    const int wn   = wid & 3;
    const int col0 = blockIdx.x * 256;

    const int t0   = blockIdx.y * p.tpc;
    const int tEnd = min(t0 + p.tpc, p.ntiles);
    if (t0 >= tEnd) return;

    const int      rA0 = wm * 32 + (lane & 7) + ((lane >> 3) & 1) * 8;
    const uint32_t xA  = (uint32_t)(rA0 & 7) << 4;
    const uint32_t kA  = (uint32_t)(lane >> 4) * 16;
    const int      rB0 = wn * 64 + ((lane >> 4) * 8) + (lane & 7);
    const uint32_t xB  = (uint32_t)(rB0 & 7) << 4;
    const uint32_t kB  = (uint32_t)((lane >> 3) & 1) * 16;
    const int mrow = lane >> 2;
    const int ncol = (lane & 3) * 2;

    // ---- load the CTA's entire B column (4 K-chunks, swizzled) once ----
#pragma unroll
    for (int i = 0; i < 16; i++) {
        int idx = i * 512 + tid;
        int kc = idx >> 11, r = (idx >> 3) & 255, ch = idx & 7;
        uint32_t so = (uint32_t)kc * PB_STGSZ + SWZ128((uint32_t)(r * 128 + ch * 16));
        cp16(sb + so, p.B + (size_t)(col0 + r) * 256 + kc * 64 + ch * 8);
    }
    cp_commit();

    for (int t = t0; t < tEnd; t++) {
        const int row0 = t * p.mstep;

        float acc[2][8][4];
#pragma unroll
        for (int i = 0; i < 2; i++)
#pragma unroll
            for (int j = 0; j < 8; j++)
#pragma unroll
                for (int q = 0; q < 4; q++) acc[i][j][q] = 0.f;

        auto loadA = [&](int kc, int s) {
            const uint32_t base = sb + PB_STG + (uint32_t)s * PB_STGSZ;
            const int koff = kc * 64;
            if (EPI == 0) {
                // fp32 A chunk -> staging (converted in place later)
#pragma unroll
                for (int i = 0; i < 4; i++) {
                    int idx = i * 512 + tid;
                    int r = idx >> 4, u = idx & 15;
                    int gr = row0 + r;
                    if (gr > p.M - 1) gr = p.M - 1;
                    cp16(base + (uint32_t)(r * 256 + u * 16),
                         p.Af + (size_t)gr * p.ldaf + koff + u * 4);
                }
            } else {
#pragma unroll
                for (int i = 0; i < 2; i++) {
                    int idx = i * 512 + tid;
                    int r = idx >> 3, ch = idx & 7;
                    uint32_t so = SWZ128((uint32_t)(r * 128 + ch * 16));
                    int gr = row0 + r;
                    if (gr > p.M - 1) gr = p.M - 1;
                    size_t ga = (size_t)gr * p.ldah + koff + ch * 8;
                    cp16(base + so,           p.Ah + ga);
                    cp16(base + 16384u + so,  p.Al + ga);
                }
            }
            cp_commit();
        };

        loadA(0, 0);
        for (int c = 0; c < 4; c++) {
            const int s = c & 1;
            asm volatile("cp.async.wait_group 0;\n" ::: "memory");
            __syncthreads();
            if (c + 1 < 4) loadA(c + 1, s ^ 1);

            if (EPI == 0) {
                // in-place fp32 -> fp16 (single pass) inside stage s
                char* stg = smem + PB_STG + s * PB_STGSZ;
                float f[2][8];
#pragma unroll
                for (int i = 0; i < 2; i++) {
                    int idx = i * 512 + tid;
                    int r = idx >> 3, ch = idx & 7;
                    const float* src = (const float*)(stg + r * 256 + ch * 32);
                    *(float4*)(f[i])     = *(const float4*)src;
                    *(float4*)(f[i] + 4) = *(const float4*)(src + 4);
                }
                __syncthreads();
#pragma unroll
                for (int i = 0; i < 2; i++) {
                    int idx = i * 512 + tid;
                    int r = idx >> 3, ch = idx & 7;
                    __half hh[8];
#pragma unroll
                    for (int q = 0; q < 8; q++) hh[q] = __float2half_rn(f[i][q]);
                    *(uint4*)(stg + SWZ128((uint32_t)(r * 128 + ch * 16))) =
                        *(const uint4*)hh;
                }
                __syncthreads();
            }

            const uint32_t baseA = sb + PB_STG + (uint32_t)s * PB_STGSZ;
            const uint32_t baseB = sb + (uint32_t)c * PB_STGSZ;
#pragma unroll
            for (int ks = 0; ks < 4; ks++) {
                const uint32_t kbA = ((uint32_t)(ks * 32) + kA) ^ xA;
                const uint32_t kbB = ((uint32_t)(ks * 32) + kB) ^ xB;
                uint32_t Ah4[2][4], Al4[2][4];
#pragma unroll
                for (int i = 0; i < 2; i++) {
                    uint32_t ro = (uint32_t)(rA0 + i * 16) * 128;
                    ldsm_x4(Ah4[i], baseA + ro + kbA);
                    if (EPI != 0) ldsm_x4(Al4[i], baseA + 16384u + ro + kbA);
                }
                uint32_t bb[4][4];
#pragma unroll
                for (int jp = 0; jp < 4; jp++)
                    ldsm_x4(bb[jp], baseB + (uint32_t)(rB0 + jp * 16) * 128 + kbB);
#pragma unroll
                for (int jp = 0; jp < 4; jp++)
#pragma unroll
                    for (int i = 0; i < 2; i++) {
                        mma16816(acc[i][2 * jp],     Ah4[i], bb[jp]);
                        mma16816(acc[i][2 * jp + 1], Ah4[i], bb[jp] + 2);
                    }
                if (EPI != 0) {
#pragma unroll
                    for (int jp = 0; jp < 4; jp++)
#pragma unroll
                        for (int i = 0; i < 2; i++) {
                            mma16816(acc[i][2 * jp],     Al4[i], bb[jp]);
                            mma16816(acc[i][2 * jp + 1], Al4[i], bb[jp] + 2);
                        }
                }
            }
        }
        __syncthreads();   // stages now free for epilogue scratch

        float* st = (float*)(smem + PB_STG);
        float* sW = st + 12000;

        if (EPI == 0 && col0 == 0) {
            // per-atom vector norms, three 42-row passes (126 rows)
            const int atom0 = row0 / 3;
#pragma unroll 1
            for (int pass = 0; pass < 3; pass++) {
                const int lo = pass * 42;
#pragma unroll
                for (int i = 0; i < 2; i++)
#pragma unroll
                    for (int half = 0; half < 2; half++) {
                        const int ml = wm * 32 + i * 16 + mrow + half * 8;
                        if (ml >= lo && ml < lo + 42) {
#pragma unroll
                            for (int j = 0; j < 8; j++) {
                                const int nl = wn * 64 + j * 8 + ncol;
                                *(float2*)(st + (size_t)(ml - lo) * SROW + nl) =
                                    make_float2(acc[i][j][half * 2],
                                                acc[i][j][half * 2 + 1]);
                            }
                        }
                    }
                __syncthreads();
                for (int idx = tid; idx < 14 * 256; idx += 512) {
                    int ai = idx >> 8, o = idx & 255;
                    int a = atom0 + pass * 14 + ai;
                    if (3 * a + 2 < p.M) {
                        float x = st[(size_t)(3 * ai)     * SROW + o];
                        float y = st[(size_t)(3 * ai + 1) * SROW + o];
                        float z = st[(size_t)(3 * ai + 2) * SROW + o];
                        float v = sqrtf(x * x + y * y + z * z);
                        __half h, l;
                        split_f16(v, h, l);
                        p.Oh[(size_t)a * 512 + 256 + o] = h;
                        p.Ol[(size_t)a * 512 + 256 + o] = l;
                    }
                }
                __syncthreads();
            }
        } else if (EPI == 2 && col0 == 256) {
            // gate -> fused stage2a, passes of 42/42/44 rows
            sW[tid] = p.Wmix2[tid];
#pragma unroll 1
            for (int pass = 0; pass < 3; pass++) {
                const int lo = pass * 42;
                const int len = (pass == 2) ? 44 : 42;
#pragma unroll
                for (int i = 0; i < 2; i++)
#pragma unroll
                    for (int half = 0; half < 2; half++) {
                        const int ml = wm * 32 + i * 16 + mrow + half * 8;
                        if (ml >= lo && ml < lo + len) {
#pragma unroll
                            for (int j = 0; j < 8; j++) {
                                const int nl = wn * 64 + j * 8 + ncol;
                                float v0 = acc[i][j][half * 2]     + p.bias[256 + nl];
                                float v1 = acc[i][j][half * 2 + 1] + p.bias[256 + nl + 1];
                                *(float2*)(st + (size_t)(ml - lo) * SROW + nl) =
                                    make_float2(v0, v1);
                            }
                        }
                    }
                __syncthreads();
                for (int rr = wid; rr < len; rr += 16) {
                    const int m = row0 + lo + rr;
                    float t00 = 0, t01 = 0, t10 = 0, t11 = 0, t20 = 0, t21 = 0;
                    if (m < p.M) {
                        const float* vwp = p.vw + (size_t)3 * m * 256;
#pragma unroll
                        for (int ii = 0; ii < 8; ii++) {
                            int o = lane + 32 * ii;
                            float ga = st[(size_t)rr * SROW + o];
                            float w0 = sW[2 * o], w1 = sW[2 * o + 1];
                            float q0 = ga * vwp[o];
                            float q1 = ga * vwp[256 + o];
                            float q2 = ga * vwp[512 + o];
                            t00 += q0 * w0; t01 += q0 * w1;
                            t10 += q1 * w0; t11 += q1 * w1;
                            t20 += q2 * w0; t21 += q2 * w1;
                        }
                    }
#pragma unroll
                    for (int off = 16; off; off >>= 1) {
                        t00 += __shfl_xor_sync(0xffffffffu, t00, off);
                        t01 += __shfl_xor_sync(0xffffffffu, t01, off);
                        t10 += __shfl_xor_sync(0xffffffffu, t10, off);
                        t11 += __shfl_xor_sync(0xffffffffu, t11, off);
                        t20 += __shfl_xor_sync(0xffffffffu, t20, off);
                        t21 += __shfl_xor_sync(0xffffffffu, t21, off);
                    }
                    if (lane == 0 && m < p.M) {
                        p.vvn2[m] = sqrtf(t00 * t00 + t10 * t10 + t20 * t20);
                        p.vw2[3 * m + 0] = t01;
                        p.vw2[3 * m + 1] = t11;
                        p.vw2[3 * m + 2] = t21;
                    }
                }
                __syncthreads();
            }
        } else if (EPI == 3) {
            // h2 -> fused stage2b, passes of 42/42/44 rows
            sW[tid] = p.W2b[tid];
            if (tid == 0) { sW[512] = p.b2b[0]; sW[513] = p.b2b[1]; }
#pragma unroll 1
            for (int pass = 0; pass < 3; pass++) {
                const int lo = pass * 42;
                const int len = (pass == 2) ? 44 : 42;
#pragma unroll
                for (int i = 0; i < 2; i++)
#pragma unroll
                    for (int half = 0; half < 2; half++) {
                        const int ml = wm * 32 + i * 16 + mrow + half * 8;
                        if (ml >= lo && ml < lo + len) {
                            const int m = row0 + ml;
                            float um = (m < p.M) ? p.u[m] : 0.f;
#pragma unroll
                            for (int j = 0; j < 8; j++) {
                                const int nl = wn * 64 + j * 8 + ncol;
                                float v0 = silu_f(acc[i][j][half * 2] +
                                                  um * p.vrow[nl] + p.bias[nl]);
                                float v1 = silu_f(acc[i][j][half * 2 + 1] +
                                                  um * p.vrow[nl + 1] + p.bias[nl + 1]);
                                *(float2*)(st + (size_t)(ml - lo) * SROW + nl) =
                                    make_float2(v0, v1);
                            }
                        }
                    }
                __syncthreads();
                for (int rr = wid; rr < len; rr += 16) {
                    const int m = row0 + lo + rr;
                    float x0 = 0, x1 = 0;
                    if (m < p.M) {
#pragma unroll
                        for (int ii = 0; ii < 8; ii++) {
                            int k = lane + 32 * ii;
                            float hv = st[(size_t)rr * SROW + k];
                            x0 += hv * sW[2 * k];
                            x1 += hv * sW[2 * k + 1];
                        }
                    }
#pragma unroll
                    for (int off = 16; off; off >>= 1) {
                        x0 += __shfl_xor_sync(0xffffffffu, x0, off);
                        x1 += __shfl_xor_sync(0xffffffffu, x1, off);
                    }
                    if (lane == 0 && m < p.M) {
                        float charge = x0 + sW[512];
                        float gate2  = x1 + sW[513];
                        int b = p.batch[m];
#pragma unroll
                        for (int cc = 0; cc < 3; cc++) {
                            float v2 = gate2 * p.vw2[3 * m + cc];
                            float y  = v2 + p.pos[3 * m + cc] * charge;
                            atomicAdd(&p.out[(size_t)b * 3 + cc], y);
                            atomicAdd(&p.out[(size_t)p.nmol * 3 + (size_t)b * 3 + cc], v2);
                        }
                    }
                }
                __syncthreads();
            }
        } else {
            // register-direct: EPI0 col256 (vW fp32), EPI2 col0 (silu->hi/lo)
#pragma unroll
            for (int i = 0; i < 2; i++) {
                const int mbase = row0 + wm * 32 + i * 16 + mrow;
#pragma unroll
                for (int half = 0; half < 2; half++) {
                    const int m = mbase + half * 8;
                    if (m >= p.M) continue;
#pragma unroll
                    for (int j = 0; j < 8; j++) {
                        const int n = col0 + wn * 64 + j * 8 + ncol;
                        float v0 = acc[i][j][half * 2 + 0];
                        float v1 = acc[i][j][half * 2 + 1];
                        if (EPI == 0) {
                            *(float2*)(p.C0 + (size_t)m * 256 + (n - 256)) =
                                make_float2(v0, v1);
                        } else {
                            v0 = silu_f(v0 + p.bias[n]);
                            v1 = silu_f(v1 + p.bias[n + 1]);
                            __half h0, l0, h1, l1;
                            split_f16(v0, h0, l0);
                            split_f16(v1, h1, l1);
                            *(__half2*)(p.Oh + (size_t)m * 256 + n) = __half2(h0, h1);
                            *(__half2*)(p.Ol + (size_t)m * 256 + n) = __half2(l0, l1);
                        }
                    }
                }
            }
            __syncthreads();
        }
    }
}

// ===========================================================================
// Streaming kernel for GEMM2 (K=512: fp32 l0 chunks then fp16 vVn chunks).
// Identical math/path to R14 EPI1.
// ===========================================================================
#define OFF_AL  16384
#define OFF_B   32768
#define OFF_F32 65536
#define STG     98304
#define SMEM_DYN (2 * STG)

__global__ void __launch_bounds__(512, 1) gemm_g2(const MP p) {
    extern __shared__ __align__(1024) char smem[];
    const uint32_t sb = smem_u32(smem);
    const int tid  = threadIdx.x;
    const int wid  = tid >> 5;
    const int lane = tid & 31;
    const int wm   = wid >> 2;
    const int wn   = wid & 3;
    const int row0 = blockIdx.y * 128;

    const int      rA0 = wm * 32 + (lane & 7) + ((lane >> 3) & 1) * 8;
    const uint32_t xA  = (uint32_t)(rA0 & 7) << 4;
    const uint32_t kA  = (uint32_t)(lane >> 4) * 16;
    const int      rB0 = wn * 64 + ((lane >> 4) * 8) + (lane & 7);
    const uint32_t xB  = (uint32_t)(rB0 & 7) << 4;
    const uint32_t kB  = (uint32_t)((lane >> 3) & 1) * 16;

    float acc[2][8][4];
#pragma unroll
    for (int i = 0; i < 2; i++)
#pragma unroll
        for (int j = 0; j < 8; j++)
#pragma unroll
            for (int q = 0; q < 4; q++) acc[i][j][q] = 0.f;

    auto load_chunk = [&](int kc, int s) {
        const uint32_t base = sb + s * STG;
        const int koff = kc * 64;
        if (koff < 256) {
#pragma unroll
            for (int i = 0; i < 4; i++) {
                int idx = i * 512 + tid;
                int r = idx >> 4, u = idx & 15;
                int gr = row0 + r;
                if (gr > p.M - 1) gr = p.M - 1;
                cp16(base + OFF_F32 + (uint32_t)(r * 256 + u * 16),
                     p.Af + (size_t)gr * 256 + koff + u * 4);
            }
        } else {
#pragma unroll
            for (int i = 0; i < 2; i++) {
                int idx = i * 512 + tid;
                int r = idx >> 3, ch = idx & 7;
                uint32_t so = SWZ128((uint32_t)(r * 128 + ch * 16));
                int gr = row0 + r;
                if (gr > p.M - 1) gr = p.M - 1;
                size_t ga = (size_t)gr * 512 + 256 + (koff - 256) + ch * 8;
                cp16(base + so,          p.Ah + ga);
                cp16(base + OFF_AL + so, p.Al + ga);
            }
        }
#pragma unroll
        for (int i = 0; i < 4; i++) {
            int idx = i * 512 + tid;
            int r = idx >> 3, ch = idx & 7;
            uint32_t so = SWZ128((uint32_t)(r * 128 + ch * 16));
            cp16(base + OFF_B + so, p.B + (size_t)r * 512 + koff + ch * 8);
        }
        cp_commit();
    };

    auto convert_stage = [&](int s) {
        char* stg = smem + s * STG;
#pragma unroll
        for (int i = 0; i < 2; i++) {
            int idx = i * 512 + tid;
            int r = idx >> 3, ch = idx & 7;
            const float* src = (const float*)(stg + OFF_F32 + r * 256 + ch * 32);
            float4 a = *(const float4*)(src);
            float4 b = *(const float4*)(src + 4);
            float f[8] = {a.x, a.y, a.z, a.w, b.x, b.y, b.z, b.w};
            __half hh[8], ll[8];
#pragma unroll
            for (int q = 0; q < 8; q++) split_f16(f[q], hh[q], ll[q]);
            uint32_t so = SWZ128((uint32_t)(r * 128 + ch * 16));
            *(uint4*)(stg + so)          = *(const uint4*)hh;
            *(uint4*)(stg + OFF_AL + so) = *(const uint4*)ll;
        }
    };

    load_chunk(0, 0);

    for (int c = 0; c < 8; c++) {
        const int s = c & 1;
        asm volatile("cp.async.wait_group 0;\n" ::: "memory");
        __syncthreads();
        if (c + 1 < 8) load_chunk(c + 1, s ^ 1);
        if (c < 4) {
            convert_stage(s);
            __syncthreads();
        }

        const uint32_t base = sb + s * STG;
#pragma unroll
        for (int ks = 0; ks < 4; ks++) {
            const uint32_t kbA = ((uint32_t)(ks * 32) + kA) ^ xA;
            const uint32_t kbB = ((uint32_t)(ks * 32) + kB) ^ xB;
            uint32_t Ah4[2][4], Al4[2][4];
#pragma unroll
            for (int i = 0; i < 2; i++) {
                uint32_t ro = (uint32_t)(rA0 + i * 16) * 128;
                ldsm_x4(Ah4[i], base + ro + kbA);
                ldsm_x4(Al4[i], base + OFF_AL + ro + kbA);
            }
            uint32_t bb[4][4];
#pragma unroll
            for (int jp = 0; jp < 4; jp++)
                ldsm_x4(bb[jp], base + OFF_B + (uint32_t)(rB0 + jp * 16) * 128 + kbB);
#pragma unroll
            for (int jp = 0; jp < 4; jp++)
#pragma unroll
                for (int i = 0; i < 2; i++) {
                    mma16816(acc[i][2 * jp],     Ah4[i], bb[jp]);
                    mma16816(acc[i][2 * jp + 1], Ah4[i], bb[jp] + 2);
                }
#pragma unroll
            for (int jp = 0; jp < 4; jp++)
#pragma unroll
                for (int i = 0; i < 2; i++) {
                    mma16816(acc[i][2 * jp],     Al4[i], bb[jp]);
                    mma16816(acc[i][2 * jp + 1], Al4[i], bb[jp] + 2);
                }
        }
    }

    const int mrow = lane >> 2;
    const int ncol = (lane & 3) * 2;
#pragma unroll
    for (int i = 0; i < 2; i++) {
        const int mbase = row0 + wm * 32 + i * 16 + mrow;
#pragma unroll
        for (int half = 0; half < 2; half++) {
            const int m = mbase + half * 8;
            if (m >= p.M) continue;
#pragma unroll
            for (int j = 0; j < 8; j++) {
                const int n = wn * 64 + j * 8 + ncol;
                float v0 = silu_f(acc[i][j][half * 2]     + p.bias[n]);
                float v1 = silu_f(acc[i][j][half * 2 + 1] + p.bias[n + 1]);
                __half h0, l0, h1, l1;
                split_f16(v0, h0, l0);
                split_f16(v1, h1, l1);
                *(__half2*)(p.Oh + (size_t)m * 256 + n) = __half2(h0, h1);
                *(__half2*)(p.Ol + (size_t)m * 256 + n) = __half2(l0, l1);
            }
        }
    }
}

// ---------------------------------------------------------------------------
// all four weight transposes (fp32 [K,N] -> fp16 [N,K]) in one launch
// ---------------------------------------------------------------------------
struct WT {
    const float *W1, *W2, *W3, *W4;
    __half *t1, *t2, *t3, *t4;
};
__global__ void wt_conv_all(const WT w) {
    int idx = blockIdx.x * blockDim.x + threadIdx.x;
    if (idx < 131072) {                       // Wmix1: K=256, N=512
        int k = idx >> 9, n = idx & 511;
        w.t1[(size_t)n * 256 + k] = __float2half_rn(w.W1[idx]);
    } else if (idx < 262144) {                // W1a: K=512, N=256
        int r = idx - 131072;
        int k = r >> 8, n = r & 255;
        w.t2[(size_t)n * 512 + k] = __float2half_rn(w.W2[r]);
    } else if (idx < 393216) {                // W2a: K=256, N=512
        int r = idx - 262144;
        int k = r >> 9, n = r & 511;
        w.t3[(size_t)n * 256 + k] = __float2half_rn(w.W3[r]);
    } else if (idx < 458752) {                // W1b[:256]: K=256, N=256
        int r = idx - 393216;
        int k = r >> 8, n = r & 255;
        w.t4[(size_t)n * 256 + k] = __float2half_rn(w.W4[r]);
    }
}

// ---------------------------------------------------------------------------
extern "C" void kernel_launch(void* const* d_in, const int* in_sizes, int n_in,
                              void* d_out, int out_size) {
    const float* pos   = (const float*)d_in[0];
    const float* l0    = (const float*)d_in[1];
    const float* l1    = (const float*)d_in[2];
    const int*   batch = (const int*)d_in[3];
    const float* Wmix1 = (const float*)d_in[4];
    const float* W1a   = (const float*)d_in[5];
    const float* b1a   = (const float*)d_in[6];
    const float* W2a   = (const float*)d_in[7];
    const float* b2a   = (const float*)d_in[8];
    const float* Wmix2 = (const float*)d_in[9];
    const float* W1b   = (const float*)d_in[10];
    const float* b1b   = (const float*)d_in[11];
    const float* W2b   = (const float*)d_in[12];
    const float* b2b   = (const float*)d_in[13];

    const int natoms = in_sizes[3];
    const int nmol   = out_size / 6;
    float* out = (float*)d_out;

    float *vw, *vvn2, *vw2;
    __half *a2h, *a2l, *a3h, *a3l, *a4h, *a4l;
    __half *bt1, *bt2, *bt3, *bt4;
    cudaGetSymbolAddress((void**)&vw,   g_vw);
    cudaGetSymbolAddress((void**)&vvn2, g_vvn2);
    cudaGetSymbolAddress((void**)&vw2,  g_vw2);
    cudaGetSymbolAddress((void**)&a2h, g_a2h);  cudaGetSymbolAddress((void**)&a2l, g_a2l);
    cudaGetSymbolAddress((void**)&a3h, g_a3h);  cudaGetSymbolAddress((void**)&a3l, g_a3l);
    cudaGetSymbolAddress((void**)&a4h, g_a4h);  cudaGetSymbolAddress((void**)&a4l, g_a4l);
    cudaGetSymbolAddress((void**)&bt1, g_bt1);
    cudaGetSymbolAddress((void**)&bt2, g_bt2);
    cudaGetSymbolAddress((void**)&bt3, g_bt3);
    cudaGetSymbolAddress((void**)&bt4, g_bt4);

    cudaFuncSetAttribute(gemm_persb<0>, cudaFuncAttributeMaxDynamicSharedMemorySize, SMEM_P);
    cudaFuncSetAttribute(gemm_persb<2>, cudaFuncAttributeMaxDynamicSharedMemorySize, SMEM_P);
    cudaFuncSetAttribute(gemm_persb<3>, cudaFuncAttributeMaxDynamicSharedMemorySize, SMEM_P);
    cudaFuncSetAttribute(gemm_g2,       cudaFuncAttributeMaxDynamicSharedMemorySize, SMEM_DYN);

    cudaMemsetAsync(d_out, 0, (size_t)out_size * sizeof(float));

    const int M1  = 3 * natoms;
    const int mt1 = (M1 + 125) / 126;
    const int mt  = (natoms + 127) / 128;
    const int GY  = 152;

    {
        WT w = {Wmix1, W1a, W2a, W1b, bt1, bt2, bt3, bt4};
        wt_conv_all<<<(458752 + 255) / 256, 256>>>(w);
    }

    // GEMM1 (persistent B, single-pass A): vmix = l1 @ Wmix1.
    {
        MP p = {};
        p.Af = l1; p.ldaf = 256;
        p.B = bt1; p.M = M1; p.K = 256; p.mstep = 126;
        p.ntiles = mt1; p.tpc = (mt1 + GY - 1) / GY;
        p.C0 = vw; p.Oh = a2h; p.Ol = a2l;
        gemm_persb<0><<<dim3(2, GY), 512, SMEM_P>>>(p);
    }

    // GEMM2 (streaming): h = silu([l0 | vVn] @ W1a + b1a) -> a3 (hi/lo).
    {
        MP p = {};
        p.Af = l0; p.Ah = a2h; p.Al = a2l;
        p.B = bt2; p.M = natoms; p.K = 512;
        p.Oh = a3h; p.Ol = a3l; p.bias = b1a;
        gemm_g2<<<dim3(1, mt), 512, SMEM_DYN>>>(p);
    }

    // GEMM3 (persistent B): col 0 -> s1 hi/lo; col 1 -> fused stage2a.
    {
        MP p = {};
        p.Ah = a3h; p.Al = a3l; p.ldah = 256;
        p.B = bt3; p.M = natoms; p.K = 256; p.mstep = 128;
        p.ntiles = mt; p.tpc = (mt + GY - 1) / GY;
        p.Oh = a4h; p.Ol = a4l; p.bias = b2a;
        p.vw = vw; p.Wmix2 = Wmix2; p.vvn2 = vvn2; p.vw2 = vw2;
        gemm_persb<2><<<dim3(2, GY), 512, SMEM_P>>>(p);
    }

    // GEMM4 (persistent B): h2 -> fused stage2b.
    {
        MP p = {};
        p.Ah = a4h; p.Al = a4l; p.ldah = 256;
        p.B = bt4; p.M = natoms; p.K = 256; p.mstep = 128;
        p.ntiles = mt; p.tpc = (mt + GY - 1) / GY;
        p.bias = b1b; p.u = vvn2; p.vrow = W1b + 256 * 256;
        p.W2b = W2b; p.b2b = b2b; p.pos = pos; p.batch = batch;
        p.vw2 = vw2; p.out = out; p.nmol = nmol;
        gemm_persb<3><<<dim3(1, GY), 512, SMEM_P>>>(p);
    }
}

// round 16
// speedup vs baseline: 1.1462x; 1.1462x over previous
#include <cuda_runtime.h>
#include <cuda_fp16.h>
#include <cstdint>
#include <cstddef>

// ---------------------------------------------------------------------------
// Dipole head: asymmetric fp16 GEMMs on mma.sync (HMMA), fp32 accum.
// R16: exact R14 structure (best known), with vW stored as fp16 instead of
//      fp32 (1.23 GB -> 0.61 GB DRAM on the vw path). GEMM1 single-pass A;
//      GEMM2/3/4 2-pass; classic wave launches.
// ---------------------------------------------------------------------------

#define NA_MAX 200000
#define MPAD   200128

// ---------------- global scratch ----------------
__device__ __align__(128) __half g_vw[(size_t)3 * NA_MAX * 256];  // vW fp16
__device__ __align__(128) __half g_a2h[(size_t)MPAD * 512];
__device__ __align__(128) __half g_a2l[(size_t)MPAD * 512];
__device__ __align__(128) __half g_a3h[(size_t)MPAD * 256];
__device__ __align__(128) __half g_a3l[(size_t)MPAD * 256];
__device__ __align__(128) __half g_a4h[(size_t)MPAD * 256];
__device__ __align__(128) __half g_a4l[(size_t)MPAD * 256];
__device__ float g_vvn2[NA_MAX];
__device__ float g_vw2[3 * NA_MAX];
__device__ __align__(128) __half g_bt1[512 * 256];
__device__ __align__(128) __half g_bt2[256 * 512];
__device__ __align__(128) __half g_bt3[512 * 256];
__device__ __align__(128) __half g_bt4[256 * 256];

// ---------------- helpers ----------------------------------------------
__device__ __forceinline__ uint32_t smem_u32(const void* p) {
    uint32_t a;
    asm("{ .reg .u64 t; cvta.to.shared.u64 t, %1; cvt.u32.u64 %0, t; }"
        : "=r"(a) : "l"(p));
    return a;
}
#define SWZ128(off) ((off) ^ (((off) >> 3) & 0x70))

__device__ __forceinline__ void cp16(uint32_t saddr, const void* gaddr) {
    asm volatile("cp.async.cg.shared.global [%0], [%1], 16;\n"
                 :: "r"(saddr), "l"(gaddr));
}
__device__ __forceinline__ void cp_commit() {
    asm volatile("cp.async.commit_group;\n" ::: "memory");
}

__device__ __forceinline__ void ldsm_x4(uint32_t* r, uint32_t a) {
    asm volatile("ldmatrix.sync.aligned.m8n8.x4.shared.b16 {%0,%1,%2,%3}, [%4];"
                 : "=r"(r[0]), "=r"(r[1]), "=r"(r[2]), "=r"(r[3]) : "r"(a));
}

__device__ __forceinline__ void mma16816(float* d, const uint32_t* a,
                                         const uint32_t* b) {
    asm volatile(
        "mma.sync.aligned.m16n8k16.row.col.f32.f16.f16.f32 "
        "{%0,%1,%2,%3}, {%4,%5,%6,%7}, {%8,%9}, {%0,%1,%2,%3};\n"
        : "+f"(d[0]), "+f"(d[1]), "+f"(d[2]), "+f"(d[3])
        : "r"(a[0]), "r"(a[1]), "r"(a[2]), "r"(a[3]), "r"(b[0]), "r"(b[1]));
}

__device__ __forceinline__ float silu_f(float x) { return x / (1.0f + __expf(-x)); }

__device__ __forceinline__ void split_f16(float v, __half& h, __half& l) {
    h = __float2half_rn(v);
    l = __float2half_rn(v - __half2float(h));
}

// ---------------------------------------------------------------------------
// HMMA GEMM, CTA tile 128x256, 512 threads, warp tile 32x64 (4m x 4n warps),
// K-chunk 64, 2-stage ring, in-loader fp32->fp16 split for k < ksplit.
// EPI 0 (GEMM1): SINGLE A pass (hi only). Others: 2-pass (hi + lo).
// ---------------------------------------------------------------------------
struct MP {
    const float*  Af;        // fp32 A source for k < ksplit
    int           ldaf;
    const __half *Ah, *Al;   // fp16 A source for k >= ksplit
    int           ldah, coffh;
    const __half *B;
    int M, K, ksplit, mstep;
    __half *vwout;           // GEMM1: vW fp16 out
    __half *Oh, *Ol;
    const float *bias, *u, *vrow;
    // fused stage2a (EPI 2):
    const __half *vw;
    const float *Wmix2;
    float *vvn2, *vw2;
    // fused stage2b (EPI 3):
    const float *W2b, *b2b, *pos;
    const int *batch;
    float *out;
    int nmol;
};

#define OFF_AL  16384
#define OFF_B   32768
#define OFF_F32 65536
#define STG     98304
#define SMEM_DYN (2 * STG)
#define SROW 264   // fp32 smem tile row stride (fused epilogues)

template <int EPI>
__global__ void __launch_bounds__(512, 1) gemm_mma(const MP p) {
    extern __shared__ __align__(1024) char smem[];
    const uint32_t sb = smem_u32(smem);
    const int tid  = threadIdx.x;
    const int wid  = tid >> 5;
    const int lane = tid & 31;
    const int wm   = wid >> 2;   // 0..3  (32-row slab)
    const int wn   = wid & 3;    // 0..3  (64-col slab)
    const int row0 = blockIdx.y * p.mstep;
    const int col0 = blockIdx.x * 256;

    const int      rA0 = wm * 32 + (lane & 7) + ((lane >> 3) & 1) * 8;
    const uint32_t xA  = (uint32_t)(rA0 & 7) << 4;
    const uint32_t kA  = (uint32_t)(lane >> 4) * 16;
    const int      rB0 = wn * 64 + ((lane >> 4) * 8) + (lane & 7);
    const uint32_t xB  = (uint32_t)(rB0 & 7) << 4;
    const uint32_t kB  = (uint32_t)((lane >> 3) & 1) * 16;

    float acc[2][8][4];
#pragma unroll
    for (int i = 0; i < 2; i++)
#pragma unroll
        for (int j = 0; j < 8; j++)
#pragma unroll
            for (int q = 0; q < 4; q++) acc[i][j][q] = 0.f;

    const int NC = p.K >> 6;   // 64-wide K chunks

    auto load_chunk = [&](int kc, int s) {
        const uint32_t base = sb + s * STG;
        const int koff = kc * 64;
        if (koff < p.ksplit) {
#pragma unroll
            for (int i = 0; i < 4; i++) {
                int idx = i * 512 + tid;
                int r = idx >> 4, u = idx & 15;
                int gr = row0 + r;
                if (gr > p.M - 1) gr = p.M - 1;
                cp16(base + OFF_F32 + (uint32_t)(r * 256 + u * 16),
                     p.Af + (size_t)gr * p.ldaf + koff + u * 4);
            }
        } else {
#pragma unroll
            for (int i = 0; i < 2; i++) {
                int idx = i * 512 + tid;
                int r = idx >> 3, ch = idx & 7;
                uint32_t so = SWZ128((uint32_t)(r * 128 + ch * 16));
                int gr = row0 + r;
                if (gr > p.M - 1) gr = p.M - 1;
                size_t ga = (size_t)gr * p.ldah + p.coffh + (koff - p.ksplit) + ch * 8;
                cp16(base + so,          p.Ah + ga);
                cp16(base + OFF_AL + so, p.Al + ga);
            }
        }
#pragma unroll
        for (int i = 0; i < 4; i++) {
            int idx = i * 512 + tid;
            int r = idx >> 3, ch = idx & 7;
            uint32_t so = SWZ128((uint32_t)(r * 128 + ch * 16));
            size_t gb = (size_t)(col0 + r) * p.K + koff + ch * 8;
            cp16(base + OFF_B + so, p.B + gb);
        }
        cp_commit();
    };

    auto convert_stage = [&](int s) {
        char* stg = smem + s * STG;
#pragma unroll
        for (int i = 0; i < 2; i++) {
            int idx = i * 512 + tid;
            int r = idx >> 3, ch = idx & 7;
            const float* src = (const float*)(stg + OFF_F32 + r * 256 + ch * 32);
            float4 a = *(const float4*)(src);
            float4 b = *(const float4*)(src + 4);
            float f[8] = {a.x, a.y, a.z, a.w, b.x, b.y, b.z, b.w};
            uint32_t so = SWZ128((uint32_t)(r * 128 + ch * 16));
            if (EPI == 0) {
                __half hh[8];
#pragma unroll
                for (int q = 0; q < 8; q++) hh[q] = __float2half_rn(f[q]);
                *(uint4*)(stg + so) = *(const uint4*)hh;
            } else {
                __half hh[8], ll[8];
#pragma unroll
                for (int q = 0; q < 8; q++) split_f16(f[q], hh[q], ll[q]);
                *(uint4*)(stg + so)          = *(const uint4*)hh;
                *(uint4*)(stg + OFF_AL + so) = *(const uint4*)ll;
            }
        }
    };

    load_chunk(0, 0);

    for (int c = 0; c < NC; c++) {
        const int s = c & 1;
        asm volatile("cp.async.wait_group 0;\n" ::: "memory");
        __syncthreads();
        if (c + 1 < NC) load_chunk(c + 1, s ^ 1);
        if ((c << 6) < p.ksplit) {
            convert_stage(s);
            __syncthreads();
        }

        const uint32_t base = sb + s * STG;
#pragma unroll
        for (int ks = 0; ks < 4; ks++) {
            const uint32_t kbA = ((uint32_t)(ks * 32) + kA) ^ xA;
            const uint32_t kbB = ((uint32_t)(ks * 32) + kB) ^ xB;
            uint32_t Ah4[2][4], Al4[2][4];
#pragma unroll
            for (int i = 0; i < 2; i++) {
                uint32_t ro = (uint32_t)(rA0 + i * 16) * 128;
                ldsm_x4(Ah4[i], base + ro + kbA);
                if (EPI != 0) ldsm_x4(Al4[i], base + OFF_AL + ro + kbA);
            }
            uint32_t bb[4][4];
#pragma unroll
            for (int jp = 0; jp < 4; jp++)
                ldsm_x4(bb[jp], base + OFF_B + (uint32_t)(rB0 + jp * 16) * 128 + kbB);

#pragma unroll
            for (int jp = 0; jp < 4; jp++)
#pragma unroll
                for (int i = 0; i < 2; i++) {
                    mma16816(acc[i][2 * jp],     Ah4[i], bb[jp]);
                    mma16816(acc[i][2 * jp + 1], Ah4[i], bb[jp] + 2);
                }
            if (EPI != 0) {
#pragma unroll
                for (int jp = 0; jp < 4; jp++)
#pragma unroll
                    for (int i = 0; i < 2; i++) {
                        mma16816(acc[i][2 * jp],     Al4[i], bb[jp]);
                        mma16816(acc[i][2 * jp + 1], Al4[i], bb[jp] + 2);
                    }
            }
        }
    }
    __syncthreads();   // retire smem tiles before epilogue reuse

    // ---------------- epilogue ----------------
    const int mrow = lane >> 2;          // 0..7
    const int ncol = (lane & 3) * 2;     // 0,2,4,6
    float* st = (float*)smem;
    float* sW = st + 128 * SROW;

    if (EPI == 0 && col0 == 0) {
        // GEMM1 vV tile: stage accumulators, compute per-atom norms.
#pragma unroll
        for (int i = 0; i < 2; i++)
#pragma unroll
            for (int half = 0; half < 2; half++) {
                const int ml = wm * 32 + i * 16 + mrow + half * 8;
#pragma unroll
                for (int j = 0; j < 8; j++) {
                    const int nl = wn * 64 + j * 8 + ncol;
                    *(float2*)(st + (size_t)ml * SROW + nl) =
                        make_float2(acc[i][j][half * 2], acc[i][j][half * 2 + 1]);
                }
            }
        __syncthreads();
        const int atom0 = row0 / 3;
#pragma unroll 2
        for (int it = 0; it < 21; it++) {
            int idx = it * 512 + tid;
            int ai = idx >> 8, o = idx & 255;
            int a = atom0 + ai;
            if (3 * a + 2 < p.M) {
                float x = st[(size_t)(3 * ai)     * SROW + o];
                float y = st[(size_t)(3 * ai + 1) * SROW + o];
                float z = st[(size_t)(3 * ai + 2) * SROW + o];
                float v = sqrtf(x * x + y * y + z * z);
                __half h, l;
                split_f16(v, h, l);
                p.Oh[(size_t)a * 512 + 256 + o] = h;
                p.Ol[(size_t)a * 512 + 256 + o] = l;
            }
        }
        return;
    }

    if (EPI == 2 && col0 == 256) {
        // gate tile -> smem, then fused stage2a (vW read as fp16).
#pragma unroll
        for (int i = 0; i < 2; i++)
#pragma unroll
            for (int half = 0; half < 2; half++) {
                const int ml = wm * 32 + i * 16 + mrow + half * 8;
#pragma unroll
                for (int j = 0; j < 8; j++) {
                    const int nl = wn * 64 + j * 8 + ncol;
                    float v0 = acc[i][j][half * 2]     + p.bias[256 + nl];
                    float v1 = acc[i][j][half * 2 + 1] + p.bias[256 + nl + 1];
                    *(float2*)(st + (size_t)ml * SROW + nl) = make_float2(v0, v1);
                }
            }
        sW[tid] = p.Wmix2[tid];
        __syncthreads();
#pragma unroll 1
        for (int t = 0; t < 8; t++) {
            const int ml = wid * 8 + t;
            const int m  = row0 + ml;
            float t00 = 0, t01 = 0, t10 = 0, t11 = 0, t20 = 0, t21 = 0;
            if (m < p.M) {
                const __half* vwp = p.vw + (size_t)3 * m * 256;
#pragma unroll
                for (int ii = 0; ii < 8; ii++) {
                    int o = lane + 32 * ii;
                    float ga = st[(size_t)ml * SROW + o];
                    float w0 = sW[2 * o], w1 = sW[2 * o + 1];
                    float q0 = ga * __half2float(vwp[o]);
                    float q1 = ga * __half2float(vwp[256 + o]);
                    float q2 = ga * __half2float(vwp[512 + o]);
                    t00 += q0 * w0; t01 += q0 * w1;
                    t10 += q1 * w0; t11 += q1 * w1;
                    t20 += q2 * w0; t21 += q2 * w1;
                }
            }
#pragma unroll
            for (int off = 16; off; off >>= 1) {
                t00 += __shfl_xor_sync(0xffffffffu, t00, off);
                t01 += __shfl_xor_sync(0xffffffffu, t01, off);
                t10 += __shfl_xor_sync(0xffffffffu, t10, off);
                t11 += __shfl_xor_sync(0xffffffffu, t11, off);
                t20 += __shfl_xor_sync(0xffffffffu, t20, off);
                t21 += __shfl_xor_sync(0xffffffffu, t21, off);
            }
            if (lane == 0 && m < p.M) {
                p.vvn2[m] = sqrtf(t00 * t00 + t10 * t10 + t20 * t20);
                p.vw2[3 * m + 0] = t01;
                p.vw2[3 * m + 1] = t11;
                p.vw2[3 * m + 2] = t21;
            }
        }
        return;
    }

    if (EPI == 3) {
        // h2 tile -> smem, then fused stage2b (final matvec + segment sums).
#pragma unroll
        for (int i = 0; i < 2; i++)
#pragma unroll
            for (int half = 0; half < 2; half++) {
                const int ml = wm * 32 + i * 16 + mrow + half * 8;
                const int m  = row0 + ml;
                float um = (m < p.M) ? p.u[m] : 0.f;
#pragma unroll
                for (int j = 0; j < 8; j++) {
                    const int nl = wn * 64 + j * 8 + ncol;
                    float v0 = silu_f(acc[i][j][half * 2] +
                                      um * p.vrow[nl] + p.bias[nl]);
                    float v1 = silu_f(acc[i][j][half * 2 + 1] +
                                      um * p.vrow[nl + 1] + p.bias[nl + 1]);
                    *(float2*)(st + (size_t)ml * SROW + nl) = make_float2(v0, v1);
                }
            }
        sW[tid] = p.W2b[tid];
        if (tid == 0) { sW[512] = p.b2b[0]; sW[513] = p.b2b[1]; }
        __syncthreads();
#pragma unroll 1
        for (int t = 0; t < 8; t++) {
            const int ml = wid * 8 + t;
            const int m  = row0 + ml;
            float x0 = 0, x1 = 0;
            if (m < p.M) {
#pragma unroll
                for (int ii = 0; ii < 8; ii++) {
                    int k = lane + 32 * ii;
                    float hv = st[(size_t)ml * SROW + k];
                    x0 += hv * sW[2 * k];
                    x1 += hv * sW[2 * k + 1];
                }
            }
#pragma unroll
            for (int off = 16; off; off >>= 1) {
                x0 += __shfl_xor_sync(0xffffffffu, x0, off);
                x1 += __shfl_xor_sync(0xffffffffu, x1, off);
            }
            if (lane == 0 && m < p.M) {
                float charge = x0 + sW[512];
                float gate2  = x1 + sW[513];
                int b = p.batch[m];
#pragma unroll
                for (int cc = 0; cc < 3; cc++) {
                    float v2 = gate2 * p.vw2[3 * m + cc];
                    float y  = v2 + p.pos[3 * m + cc] * charge;
                    atomicAdd(&p.out[(size_t)b * 3 + cc], y);
                    atomicAdd(&p.out[(size_t)p.nmol * 3 + (size_t)b * 3 + cc], v2);
                }
            }
        }
        return;
    }

    // Generic register epilogues (EPI 0 col 256, EPI 1, EPI 2 col 0)
#pragma unroll
    for (int i = 0; i < 2; i++) {
        const int mbase = row0 + wm * 32 + i * 16 + mrow;
#pragma unroll
        for (int half = 0; half < 2; half++) {
            const int m = mbase + half * 8;
            if (m >= p.M) continue;
#pragma unroll
            for (int j = 0; j < 8; j++) {
                const int n = col0 + wn * 64 + j * 8 + ncol;
                float v0 = acc[i][j][half * 2 + 0];
                float v1 = acc[i][j][half * 2 + 1];
                if (EPI == 0) {
                    // GEMM1 vW tile: fp16 -> vwout (ld 256)
                    *(__half2*)(p.vwout + (size_t)m * 256 + (n - 256)) =
                        __half2(__float2half_rn(v0), __float2half_rn(v1));
                } else {
                    v0 = silu_f(v0 + p.bias[n]);
                    v1 = silu_f(v1 + p.bias[n + 1]);
                    __half h0, l0, h1, l1;
                    split_f16(v0, h0, l0);
                    split_f16(v1, h1, l1);
                    *(__half2*)(p.Oh + (size_t)m * 256 + n) = __half2(h0, h1);
                    *(__half2*)(p.Ol + (size_t)m * 256 + n) = __half2(l0, l1);
                }
            }
        }
    }
}

// ---------------------------------------------------------------------------
// all four weight transposes (fp32 [K,N] -> fp16 [N,K]) in one launch
// ---------------------------------------------------------------------------
struct WT {
    const float *W1, *W2, *W3, *W4;
    __half *t1, *t2, *t3, *t4;
};
__global__ void wt_conv_all(const WT w) {
    int idx = blockIdx.x * blockDim.x + threadIdx.x;
    if (idx < 131072) {                       // Wmix1: K=256, N=512
        int k = idx >> 9, n = idx & 511;
        w.t1[(size_t)n * 256 + k] = __float2half_rn(w.W1[idx]);
    } else if (idx < 262144) {                // W1a: K=512, N=256
        int r = idx - 131072;
        int k = r >> 8, n = r & 255;
        w.t2[(size_t)n * 512 + k] = __float2half_rn(w.W2[r]);
    } else if (idx < 393216) {                // W2a: K=256, N=512
        int r = idx - 262144;
        int k = r >> 9, n = r & 511;
        w.t3[(size_t)n * 256 + k] = __float2half_rn(w.W3[r]);
    } else if (idx < 458752) {                // W1b[:256]: K=256, N=256
        int r = idx - 393216;
        int k = r >> 8, n = r & 255;
        w.t4[(size_t)n * 256 + k] = __float2half_rn(w.W4[r]);
    }
}

// ---------------------------------------------------------------------------
extern "C" void kernel_launch(void* const* d_in, const int* in_sizes, int n_in,
                              void* d_out, int out_size) {
    const float* pos   = (const float*)d_in[0];
    const float* l0    = (const float*)d_in[1];
    const float* l1    = (const float*)d_in[2];
    const int*   batch = (const int*)d_in[3];
    const float* Wmix1 = (const float*)d_in[4];
    const float* W1a   = (const float*)d_in[5];
    const float* b1a   = (const float*)d_in[6];
    const float* W2a   = (const float*)d_in[7];
    const float* b2a   = (const float*)d_in[8];
    const float* Wmix2 = (const float*)d_in[9];
    const float* W1b   = (const float*)d_in[10];
    const float* b1b   = (const float*)d_in[11];
    const float* W2b   = (const float*)d_in[12];
    const float* b2b   = (const float*)d_in[13];

    const int natoms = in_sizes[3];
    const int nmol   = out_size / 6;
    float* out = (float*)d_out;

    float *vvn2, *vw2;
    __half *vw;
    __half *a2h, *a2l, *a3h, *a3l, *a4h, *a4l;
    __half *bt1, *bt2, *bt3, *bt4;
    cudaGetSymbolAddress((void**)&vw,   g_vw);
    cudaGetSymbolAddress((void**)&vvn2, g_vvn2);
    cudaGetSymbolAddress((void**)&vw2,  g_vw2);
    cudaGetSymbolAddress((void**)&a2h, g_a2h);  cudaGetSymbolAddress((void**)&a2l, g_a2l);
    cudaGetSymbolAddress((void**)&a3h, g_a3h);  cudaGetSymbolAddress((void**)&a3l, g_a3l);
    cudaGetSymbolAddress((void**)&a4h, g_a4h);  cudaGetSymbolAddress((void**)&a4l, g_a4l);
    cudaGetSymbolAddress((void**)&bt1, g_bt1);
    cudaGetSymbolAddress((void**)&bt2, g_bt2);
    cudaGetSymbolAddress((void**)&bt3, g_bt3);
    cudaGetSymbolAddress((void**)&bt4, g_bt4);

    cudaFuncSetAttribute(gemm_mma<0>, cudaFuncAttributeMaxDynamicSharedMemorySize, SMEM_DYN);
    cudaFuncSetAttribute(gemm_mma<1>, cudaFuncAttributeMaxDynamicSharedMemorySize, SMEM_DYN);
    cudaFuncSetAttribute(gemm_mma<2>, cudaFuncAttributeMaxDynamicSharedMemorySize, SMEM_DYN);
    cudaFuncSetAttribute(gemm_mma<3>, cudaFuncAttributeMaxDynamicSharedMemorySize, SMEM_DYN);

    cudaMemsetAsync(d_out, 0, (size_t)out_size * sizeof(float));

    const int M1  = 3 * natoms;
    const int mt1 = (M1 + 125) / 126;          // GEMM1: 126-row tiles (42 atoms)
    const int mt  = (natoms + 127) / 128;

    {
        WT w = {Wmix1, W1a, W2a, W1b, bt1, bt2, bt3, bt4};
        wt_conv_all<<<(458752 + 255) / 256, 256>>>(w);
    }

    // GEMM1 (single-pass A): vmix = l1 @ Wmix1 (3N x 512).
    // col 0 -> fused vVn; col 1 -> vW (fp16).
    {
        MP p = {};
        p.Af = l1; p.ldaf = 256; p.ksplit = 256;
        p.Ah = a2h; p.Al = a2l; p.ldah = 512; p.coffh = 0;
        p.B = bt1; p.M = M1; p.K = 256; p.mstep = 126;
        p.vwout = vw; p.Oh = a2h; p.Ol = a2l;
        gemm_mma<0><<<dim3(2, mt1), 512, SMEM_DYN>>>(p);
    }

    // GEMM2: h = silu([l0 | vVn] @ W1a + b1a) -> a3 (hi/lo).
    {
        MP p = {};
        p.Af = l0; p.ldaf = 256; p.ksplit = 256;
        p.Ah = a2h; p.Al = a2l; p.ldah = 512; p.coffh = 256;
        p.B = bt2; p.M = natoms; p.K = 512; p.mstep = 128;
        p.Oh = a3h; p.Ol = a3l; p.bias = b1a;
        gemm_mma<1><<<dim3(1, mt), 512, SMEM_DYN>>>(p);
    }

    // GEMM3: x = h @ W2a + b2a. col 0: s1 -> a4 hi/lo; col 1: fused stage2a.
    {
        MP p = {};
        p.Af = nullptr; p.ldaf = 256; p.ksplit = 0;
        p.Ah = a3h; p.Al = a3l; p.ldah = 256; p.coffh = 0;
        p.B = bt3; p.M = natoms; p.K = 256; p.mstep = 128;
        p.Oh = a4h; p.Ol = a4l; p.bias = b2a;
        p.vw = vw; p.Wmix2 = Wmix2; p.vvn2 = vvn2; p.vw2 = vw2;
        gemm_mma<2><<<dim3(2, mt), 512, SMEM_DYN>>>(p);
    }

    // GEMM4: h2 = silu(s1 @ W1b + vvn2*vrow + b1b) -> fused stage2b.
    {
        MP p = {};
        p.Af = nullptr; p.ldaf = 256; p.ksplit = 0;
        p.Ah = a4h; p.Al = a4l; p.ldah = 256; p.coffh = 0;
        p.B = bt4; p.M = natoms; p.K = 256; p.mstep = 128;
        p.bias = b1b; p.u = vvn2; p.vrow = W1b + 256 * 256;
        p.W2b = W2b; p.b2b = b2b; p.pos = pos; p.batch = batch;
        p.vw2 = vw2; p.out = out; p.nmol = nmol;
        gemm_mma<3><<<dim3(1, mt), 512, SMEM_DYN>>>(p);
    }
}

// round 17
// speedup vs baseline: 1.1597x; 1.0118x over previous
#include <cuda_runtime.h>
#include <cuda_fp16.h>
#include <cstdint>
#include <cstddef>

// ---------------------------------------------------------------------------
// Dipole head: asymmetric fp16 GEMMs on mma.sync (HMMA), fp32 accum.
// R17: (1) 3-stage cp.async ring for GEMM1/3/4 (64KB stages, GEMM1 converts
//      fp32 A in place); (2) l0 single-pass in GEMM2 (raw input, like l1);
//      (3) vectorized stage2a/2b fused epilogues.
// vW fp16; GEMM1 single-pass; classic wave launches.
// ---------------------------------------------------------------------------

#define NA_MAX 200000
#define MPAD   200128

// ---------------- global scratch ----------------
__device__ __align__(128) __half g_vw[(size_t)3 * NA_MAX * 256];  // vW fp16
__device__ __align__(128) __half g_a2h[(size_t)MPAD * 512];
__device__ __align__(128) __half g_a2l[(size_t)MPAD * 512];
__device__ __align__(128) __half g_a3h[(size_t)MPAD * 256];
__device__ __align__(128) __half g_a3l[(size_t)MPAD * 256];
__device__ __align__(128) __half g_a4h[(size_t)MPAD * 256];
__device__ __align__(128) __half g_a4l[(size_t)MPAD * 256];
__device__ float g_vvn2[NA_MAX];
__device__ float g_vw2[3 * NA_MAX];
__device__ __align__(128) __half g_bt1[512 * 256];
__device__ __align__(128) __half g_bt2[256 * 512];
__device__ __align__(128) __half g_bt3[512 * 256];
__device__ __align__(128) __half g_bt4[256 * 256];

// ---------------- helpers ----------------------------------------------
__device__ __forceinline__ uint32_t smem_u32(const void* p) {
    uint32_t a;
    asm("{ .reg .u64 t; cvta.to.shared.u64 t, %1; cvt.u32.u64 %0, t; }"
        : "=r"(a) : "l"(p));
    return a;
}
#define SWZ128(off) ((off) ^ (((off) >> 3) & 0x70))

__device__ __forceinline__ void cp16(uint32_t saddr, const void* gaddr) {
    asm volatile("cp.async.cg.shared.global [%0], [%1], 16;\n"
                 :: "r"(saddr), "l"(gaddr));
}
__device__ __forceinline__ void cp_commit() {
    asm volatile("cp.async.commit_group;\n" ::: "memory");
}

__device__ __forceinline__ void ldsm_x4(uint32_t* r, uint32_t a) {
    asm volatile("ldmatrix.sync.aligned.m8n8.x4.shared.b16 {%0,%1,%2,%3}, [%4];"
                 : "=r"(r[0]), "=r"(r[1]), "=r"(r[2]), "=r"(r[3]) : "r"(a));
}

__device__ __forceinline__ void mma16816(float* d, const uint32_t* a,
                                         const uint32_t* b) {
    asm volatile(
        "mma.sync.aligned.m16n8k16.row.col.f32.f16.f16.f32 "
        "{%0,%1,%2,%3}, {%4,%5,%6,%7}, {%8,%9}, {%0,%1,%2,%3};\n"
        : "+f"(d[0]), "+f"(d[1]), "+f"(d[2]), "+f"(d[3])
        : "r"(a[0]), "r"(a[1]), "r"(a[2]), "r"(a[3]), "r"(b[0]), "r"(b[1]));
}

__device__ __forceinline__ float silu_f(float x) { return x / (1.0f + __expf(-x)); }

__device__ __forceinline__ void split_f16(float v, __half& h, __half& l) {
    h = __float2half_rn(v);
    l = __float2half_rn(v - __half2float(h));
}

// ---------------------------------------------------------------------------
struct MP {
    const float*  Af;        // fp32 A source for k < ksplit
    int           ldaf;
    const __half *Ah, *Al;   // fp16 A source for k >= ksplit
    int           ldah, coffh;
    const __half *B;
    int M, K, ksplit, mstep;
    __half *vwout;           // GEMM1: vW fp16 out
    __half *Oh, *Ol;
    const float *bias, *u, *vrow;
    // fused stage2a (EPI 2):
    const __half *vw;
    const float *Wmix2;
    float *vvn2, *vw2;
    // fused stage2b (EPI 3):
    const float *W2b, *b2b, *pos;
    const int *batch;
    float *out;
    int nmol;
};

#define OFF_AL  16384
#define OFF_B   32768
#define SMEM_ALL 196608
#define SROW 264   // fp32 smem tile row stride (fused epilogues)

// EPI 0: GEMM1 (single-pass A, fp32 in-place convert, 3-stage 64KB)
// EPI 1: GEMM2 (l0 single-pass chunks 0-3, vVn 2-pass chunks 4-7, 2-stage 96KB)
// EPI 2: GEMM3 (2-pass, 3-stage 64KB)
// EPI 3: GEMM4 (2-pass, 3-stage 64KB)
template <int EPI>
__global__ void __launch_bounds__(512, 1) gemm_mma(const MP p) {
    constexpr int      NSTG = (EPI == 1) ? 2 : 3;
    constexpr uint32_t STGE = (EPI == 1) ? 98304u : 65536u;
    extern __shared__ __align__(1024) char smem[];
    const uint32_t sb = smem_u32(smem);
    const int tid  = threadIdx.x;
    const int wid  = tid >> 5;
    const int lane = tid & 31;
    const int wm   = wid >> 2;   // 0..3  (32-row slab)
    const int wn   = wid & 3;    // 0..3  (64-col slab)
    const int row0 = blockIdx.y * p.mstep;
    const int col0 = blockIdx.x * 256;

    const int      rA0 = wm * 32 + (lane & 7) + ((lane >> 3) & 1) * 8;
    const uint32_t xA  = (uint32_t)(rA0 & 7) << 4;
    const uint32_t kA  = (uint32_t)(lane >> 4) * 16;
    const int      rB0 = wn * 64 + ((lane >> 4) * 8) + (lane & 7);
    const uint32_t xB  = (uint32_t)(rB0 & 7) << 4;
    const uint32_t kB  = (uint32_t)((lane >> 3) & 1) * 16;

    float acc[2][8][4];
#pragma unroll
    for (int i = 0; i < 2; i++)
#pragma unroll
        for (int j = 0; j < 8; j++)
#pragma unroll
            for (int q = 0; q < 4; q++) acc[i][j][q] = 0.f;

    const int NC = p.K >> 6;   // 64-wide K chunks

    auto load_chunk = [&](int kc, int s) {
        const uint32_t base = sb + (uint32_t)s * STGE;
        const int koff = kc * 64;
        if (EPI <= 1 && koff < p.ksplit) {
            // fp32 A chunk -> staging (EPI0: A area in place; EPI1: at 64KB)
            const uint32_t fo = (EPI == 0) ? 0u : 65536u;
#pragma unroll
            for (int i = 0; i < 4; i++) {
                int idx = i * 512 + tid;
                int r = idx >> 4, u = idx & 15;
                int gr = row0 + r;
                if (gr > p.M - 1) gr = p.M - 1;
                cp16(base + fo + (uint32_t)(r * 256 + u * 16),
                     p.Af + (size_t)gr * p.ldaf + koff + u * 4);
            }
        } else {
#pragma unroll
            for (int i = 0; i < 2; i++) {
                int idx = i * 512 + tid;
                int r = idx >> 3, ch = idx & 7;
                uint32_t so = SWZ128((uint32_t)(r * 128 + ch * 16));
                int gr = row0 + r;
                if (gr > p.M - 1) gr = p.M - 1;
                size_t ga = (size_t)gr * p.ldah + p.coffh + (koff - p.ksplit) + ch * 8;
                cp16(base + so,          p.Ah + ga);
                cp16(base + OFF_AL + so, p.Al + ga);
            }
        }
#pragma unroll
        for (int i = 0; i < 4; i++) {
            int idx = i * 512 + tid;
            int r = idx >> 3, ch = idx & 7;
            uint32_t so = SWZ128((uint32_t)(r * 128 + ch * 16));
            size_t gb = (size_t)(col0 + r) * p.K + koff + ch * 8;
            cp16(base + OFF_B + so, p.B + gb);
        }
        cp_commit();
    };

    // single-pass fp32 -> fp16 conversion (EPI0 in place, EPI1 from 64KB)
    auto convert_stage = [&](int s) {
        char* stg = smem + (size_t)s * STGE;
        const uint32_t fo = (EPI == 0) ? 0u : 65536u;
        float f[2][8];
#pragma unroll
        for (int i = 0; i < 2; i++) {
            int idx = i * 512 + tid;
            int r = idx >> 3, ch = idx & 7;
            const float* src = (const float*)(stg + fo + r * 256 + ch * 32);
            *(float4*)(f[i])     = *(const float4*)(src);
            *(float4*)(f[i] + 4) = *(const float4*)(src + 4);
        }
        if (EPI == 0) __syncthreads();   // in-place: all reads before writes
#pragma unroll
        for (int i = 0; i < 2; i++) {
            int idx = i * 512 + tid;
            int r = idx >> 3, ch = idx & 7;
            __half hh[8];
#pragma unroll
            for (int q = 0; q < 8; q++) hh[q] = __float2half_rn(f[i][q]);
            *(uint4*)(stg + SWZ128((uint32_t)(r * 128 + ch * 16))) =
                *(const uint4*)hh;
        }
    };

    load_chunk(0, 0);
    if (NSTG == 3 && NC > 1) load_chunk(1, 1);

    for (int c = 0; c < NC; c++) {
        const int s = c % NSTG;
        if (NSTG == 3 && c + 1 < NC)
            asm volatile("cp.async.wait_group 1;\n" ::: "memory");
        else
            asm volatile("cp.async.wait_group 0;\n" ::: "memory");
        __syncthreads();
        const int nxt = c + NSTG - 1;
        if (nxt < NC) load_chunk(nxt, nxt % NSTG);

        const int koff = c * 64;
        if (EPI <= 1 && koff < p.ksplit) {
            convert_stage(s);
            __syncthreads();
        }
        const bool dolo = (EPI != 0) && (koff >= p.ksplit);

        const uint32_t base = sb + (uint32_t)s * STGE;
#pragma unroll
        for (int ks = 0; ks < 4; ks++) {
            const uint32_t kbA = ((uint32_t)(ks * 32) + kA) ^ xA;
            const uint32_t kbB = ((uint32_t)(ks * 32) + kB) ^ xB;
            uint32_t Ah4[2][4], Al4[2][4];
#pragma unroll
            for (int i = 0; i < 2; i++) {
                uint32_t ro = (uint32_t)(rA0 + i * 16) * 128;
                ldsm_x4(Ah4[i], base + ro + kbA);
                if (dolo) ldsm_x4(Al4[i], base + OFF_AL + ro + kbA);
            }
            uint32_t bb[4][4];
#pragma unroll
            for (int jp = 0; jp < 4; jp++)
                ldsm_x4(bb[jp], base + OFF_B + (uint32_t)(rB0 + jp * 16) * 128 + kbB);

#pragma unroll
            for (int jp = 0; jp < 4; jp++)
#pragma unroll
                for (int i = 0; i < 2; i++) {
                    mma16816(acc[i][2 * jp],     Ah4[i], bb[jp]);
                    mma16816(acc[i][2 * jp + 1], Ah4[i], bb[jp] + 2);
                }
            if (dolo) {
#pragma unroll
                for (int jp = 0; jp < 4; jp++)
#pragma unroll
                    for (int i = 0; i < 2; i++) {
                        mma16816(acc[i][2 * jp],     Al4[i], bb[jp]);
                        mma16816(acc[i][2 * jp + 1], Al4[i], bb[jp] + 2);
                    }
            }
        }
    }
    __syncthreads();   // retire smem tiles before epilogue reuse

    // ---------------- epilogue ----------------
    const int mrow = lane >> 2;          // 0..7
    const int ncol = (lane & 3) * 2;     // 0,2,4,6
    float* st = (float*)smem;
    float* sW = st + 128 * SROW;

    if (EPI == 0 && col0 == 0) {
        // GEMM1 vV tile: stage accumulators, compute per-atom norms.
#pragma unroll
        for (int i = 0; i < 2; i++)
#pragma unroll
            for (int half = 0; half < 2; half++) {
                const int ml = wm * 32 + i * 16 + mrow + half * 8;
#pragma unroll
                for (int j = 0; j < 8; j++) {
                    const int nl = wn * 64 + j * 8 + ncol;
                    *(float2*)(st + (size_t)ml * SROW + nl) =
                        make_float2(acc[i][j][half * 2], acc[i][j][half * 2 + 1]);
                }
            }
        __syncthreads();
        const int atom0 = row0 / 3;
#pragma unroll 2
        for (int it = 0; it < 21; it++) {
            int idx = it * 512 + tid;
            int ai = idx >> 8, o = idx & 255;
            int a = atom0 + ai;
            if (3 * a + 2 < p.M) {
                float x = st[(size_t)(3 * ai)     * SROW + o];
                float y = st[(size_t)(3 * ai + 1) * SROW + o];
                float z = st[(size_t)(3 * ai + 2) * SROW + o];
                float v = sqrtf(x * x + y * y + z * z);
                __half h, l;
                split_f16(v, h, l);
                p.Oh[(size_t)a * 512 + 256 + o] = h;
                p.Ol[(size_t)a * 512 + 256 + o] = l;
            }
        }
        return;
    }

    if (EPI == 2 && col0 == 256) {
        // gate tile -> smem, then fused stage2a (vectorized, vW fp16).
#pragma unroll
        for (int i = 0; i < 2; i++)
#pragma unroll
            for (int half = 0; half < 2; half++) {
                const int ml = wm * 32 + i * 16 + mrow + half * 8;
#pragma unroll
                for (int j = 0; j < 8; j++) {
                    const int nl = wn * 64 + j * 8 + ncol;
                    float v0 = acc[i][j][half * 2]     + p.bias[256 + nl];
                    float v1 = acc[i][j][half * 2 + 1] + p.bias[256 + nl + 1];
                    *(float2*)(st + (size_t)ml * SROW + nl) = make_float2(v0, v1);
                }
            }
        sW[tid] = p.Wmix2[tid];
        __syncthreads();
        const int ob = lane * 8;
#pragma unroll 1
        for (int t = 0; t < 8; t++) {
            const int ml = wid * 8 + t;
            const int m  = row0 + ml;
            float t00 = 0, t01 = 0, t10 = 0, t11 = 0, t20 = 0, t21 = 0;
            if (m < p.M) {
                const float* gp = st + (size_t)ml * SROW + ob;
                float ga[8];
                *(float4*)(ga)     = *(const float4*)(gp);
                *(float4*)(ga + 4) = *(const float4*)(gp + 4);
                const __half* vwp = p.vw + (size_t)3 * m * 256 + ob;
                __half v0[8], v1[8], v2[8];
                *(uint4*)v0 = *(const uint4*)(vwp);
                *(uint4*)v1 = *(const uint4*)(vwp + 256);
                *(uint4*)v2 = *(const uint4*)(vwp + 512);
                float wv[16];
                *(float4*)(wv)      = *(const float4*)(sW + 2 * ob);
                *(float4*)(wv + 4)  = *(const float4*)(sW + 2 * ob + 4);
                *(float4*)(wv + 8)  = *(const float4*)(sW + 2 * ob + 8);
                *(float4*)(wv + 12) = *(const float4*)(sW + 2 * ob + 12);
#pragma unroll
                for (int q = 0; q < 8; q++) {
                    float w0 = wv[2 * q], w1 = wv[2 * q + 1];
                    float q0 = ga[q] * __half2float(v0[q]);
                    float q1 = ga[q] * __half2float(v1[q]);
                    float q2 = ga[q] * __half2float(v2[q]);
                    t00 += q0 * w0; t01 += q0 * w1;
                    t10 += q1 * w0; t11 += q1 * w1;
                    t20 += q2 * w0; t21 += q2 * w1;
                }
            }
#pragma unroll
            for (int off = 16; off; off >>= 1) {
                t00 += __shfl_xor_sync(0xffffffffu, t00, off);
                t01 += __shfl_xor_sync(0xffffffffu, t01, off);
                t10 += __shfl_xor_sync(0xffffffffu, t10, off);
                t11 += __shfl_xor_sync(0xffffffffu, t11, off);
                t20 += __shfl_xor_sync(0xffffffffu, t20, off);
                t21 += __shfl_xor_sync(0xffffffffu, t21, off);
            }
            if (lane == 0 && m < p.M) {
                p.vvn2[m] = sqrtf(t00 * t00 + t10 * t10 + t20 * t20);
                p.vw2[3 * m + 0] = t01;
                p.vw2[3 * m + 1] = t11;
                p.vw2[3 * m + 2] = t21;
            }
        }
        return;
    }

    if (EPI == 3) {
        // h2 tile -> smem, then fused stage2b (vectorized matvec + seg sums).
#pragma unroll
        for (int i = 0; i < 2; i++)
#pragma unroll
            for (int half = 0; half < 2; half++) {
                const int ml = wm * 32 + i * 16 + mrow + half * 8;
                const int m  = row0 + ml;
                float um = (m < p.M) ? p.u[m] : 0.f;
#pragma unroll
                for (int j = 0; j < 8; j++) {
                    const int nl = wn * 64 + j * 8 + ncol;
                    float v0 = silu_f(acc[i][j][half * 2] +
                                      um * p.vrow[nl] + p.bias[nl]);
                    float v1 = silu_f(acc[i][j][half * 2 + 1] +
                                      um * p.vrow[nl + 1] + p.bias[nl + 1]);
                    *(float2*)(st + (size_t)ml * SROW + nl) = make_float2(v0, v1);
                }
            }
        sW[tid] = p.W2b[tid];
        if (tid == 0) { sW[512] = p.b2b[0]; sW[513] = p.b2b[1]; }
        __syncthreads();
        const int ob = lane * 8;
#pragma unroll 1
        for (int t = 0; t < 8; t++) {
            const int ml = wid * 8 + t;
            const int m  = row0 + ml;
            float x0 = 0, x1 = 0;
            if (m < p.M) {
                const float* hp = st + (size_t)ml * SROW + ob;
                float hv[8];
                *(float4*)(hv)     = *(const float4*)(hp);
                *(float4*)(hv + 4) = *(const float4*)(hp + 4);
                float wv[16];
                *(float4*)(wv)      = *(const float4*)(sW + 2 * ob);
                *(float4*)(wv + 4)  = *(const float4*)(sW + 2 * ob + 4);
                *(float4*)(wv + 8)  = *(const float4*)(sW + 2 * ob + 8);
                *(float4*)(wv + 12) = *(const float4*)(sW + 2 * ob + 12);
#pragma unroll
                for (int q = 0; q < 8; q++) {
                    x0 += hv[q] * wv[2 * q];
                    x1 += hv[q] * wv[2 * q + 1];
                }
            }
#pragma unroll
            for (int off = 16; off; off >>= 1) {
                x0 += __shfl_xor_sync(0xffffffffu, x0, off);
                x1 += __shfl_xor_sync(0xffffffffu, x1, off);
            }
            if (lane == 0 && m < p.M) {
                float charge = x0 + sW[512];
                float gate2  = x1 + sW[513];
                int b = p.batch[m];
#pragma unroll
                for (int cc = 0; cc < 3; cc++) {
                    float v2 = gate2 * p.vw2[3 * m + cc];
                    float y  = v2 + p.pos[3 * m + cc] * charge;
                    atomicAdd(&p.out[(size_t)b * 3 + cc], y);
                    atomicAdd(&p.out[(size_t)p.nmol * 3 + (size_t)b * 3 + cc], v2);
                }
            }
        }
        return;
    }

    // Generic register epilogues (EPI 0 col 256, EPI 1, EPI 2 col 0)
#pragma unroll
    for (int i = 0; i < 2; i++) {
        const int mbase = row0 + wm * 32 + i * 16 + mrow;
#pragma unroll
        for (int half = 0; half < 2; half++) {
            const int m = mbase + half * 8;
            if (m >= p.M) continue;
#pragma unroll
            for (int j = 0; j < 8; j++) {
                const int n = col0 + wn * 64 + j * 8 + ncol;
                float v0 = acc[i][j][half * 2 + 0];
                float v1 = acc[i][j][half * 2 + 1];
                if (EPI == 0) {
                    *(__half2*)(p.vwout + (size_t)m * 256 + (n - 256)) =
                        __half2(__float2half_rn(v0), __float2half_rn(v1));
                } else {
                    v0 = silu_f(v0 + p.bias[n]);
                    v1 = silu_f(v1 + p.bias[n + 1]);
                    __half h0, l0, h1, l1;
                    split_f16(v0, h0, l0);
                    split_f16(v1, h1, l1);
                    *(__half2*)(p.Oh + (size_t)m * 256 + n) = __half2(h0, h1);
                    *(__half2*)(p.Ol + (size_t)m * 256 + n) = __half2(l0, l1);
                }
            }
        }
    }
}

// ---------------------------------------------------------------------------
// all four weight transposes (fp32 [K,N] -> fp16 [N,K]) in one launch
// ---------------------------------------------------------------------------
struct WT {
    const float *W1, *W2, *W3, *W4;
    __half *t1, *t2, *t3, *t4;
};
__global__ void wt_conv_all(const WT w) {
    int idx = blockIdx.x * blockDim.x + threadIdx.x;
    if (idx < 131072) {                       // Wmix1: K=256, N=512
        int k = idx >> 9, n = idx & 511;
        w.t1[(size_t)n * 256 + k] = __float2half_rn(w.W1[idx]);
    } else if (idx < 262144) {                // W1a: K=512, N=256
        int r = idx - 131072;
        int k = r >> 8, n = r & 255;
        w.t2[(size_t)n * 512 + k] = __float2half_rn(w.W2[r]);
    } else if (idx < 393216) {                // W2a: K=256, N=512
        int r = idx - 262144;
        int k = r >> 9, n = r & 511;
        w.t3[(size_t)n * 256 + k] = __float2half_rn(w.W3[r]);
    } else if (idx < 458752) {                // W1b[:256]: K=256, N=256
        int r = idx - 393216;
        int k = r >> 8, n = r & 255;
        w.t4[(size_t)n * 256 + k] = __float2half_rn(w.W4[r]);
    }
}

// ---------------------------------------------------------------------------
extern "C" void kernel_launch(void* const* d_in, const int* in_sizes, int n_in,
                              void* d_out, int out_size) {
    const float* pos   = (const float*)d_in[0];
    const float* l0    = (const float*)d_in[1];
    const float* l1    = (const float*)d_in[2];
    const int*   batch = (const int*)d_in[3];
    const float* Wmix1 = (const float*)d_in[4];
    const float* W1a   = (const float*)d_in[5];
    const float* b1a   = (const float*)d_in[6];
    const float* W2a   = (const float*)d_in[7];
    const float* b2a   = (const float*)d_in[8];
    const float* Wmix2 = (const float*)d_in[9];
    const float* W1b   = (const float*)d_in[10];
    const float* b1b   = (const float*)d_in[11];
    const float* W2b   = (const float*)d_in[12];
    const float* b2b   = (const float*)d_in[13];

    const int natoms = in_sizes[3];
    const int nmol   = out_size / 6;
    float* out = (float*)d_out;

    float *vvn2, *vw2;
    __half *vw;
    __half *a2h, *a2l, *a3h, *a3l, *a4h, *a4l;
    __half *bt1, *bt2, *bt3, *bt4;
    cudaGetSymbolAddress((void**)&vw,   g_vw);
    cudaGetSymbolAddress((void**)&vvn2, g_vvn2);
    cudaGetSymbolAddress((void**)&vw2,  g_vw2);
    cudaGetSymbolAddress((void**)&a2h, g_a2h);  cudaGetSymbolAddress((void**)&a2l, g_a2l);
    cudaGetSymbolAddress((void**)&a3h, g_a3h);  cudaGetSymbolAddress((void**)&a3l, g_a3l);
    cudaGetSymbolAddress((void**)&a4h, g_a4h);  cudaGetSymbolAddress((void**)&a4l, g_a4l);
    cudaGetSymbolAddress((void**)&bt1, g_bt1);
    cudaGetSymbolAddress((void**)&bt2, g_bt2);
    cudaGetSymbolAddress((void**)&bt3, g_bt3);
    cudaGetSymbolAddress((void**)&bt4, g_bt4);

    cudaFuncSetAttribute(gemm_mma<0>, cudaFuncAttributeMaxDynamicSharedMemorySize, SMEM_ALL);
    cudaFuncSetAttribute(gemm_mma<1>, cudaFuncAttributeMaxDynamicSharedMemorySize, SMEM_ALL);
    cudaFuncSetAttribute(gemm_mma<2>, cudaFuncAttributeMaxDynamicSharedMemorySize, SMEM_ALL);
    cudaFuncSetAttribute(gemm_mma<3>, cudaFuncAttributeMaxDynamicSharedMemorySize, SMEM_ALL);

    cudaMemsetAsync(d_out, 0, (size_t)out_size * sizeof(float));

    const int M1  = 3 * natoms;
    const int mt1 = (M1 + 125) / 126;          // GEMM1: 126-row tiles (42 atoms)
    const int mt  = (natoms + 127) / 128;

    {
        WT w = {Wmix1, W1a, W2a, W1b, bt1, bt2, bt3, bt4};
        wt_conv_all<<<(458752 + 255) / 256, 256>>>(w);
    }

    // GEMM1 (single-pass A, 3-stage): vmix = l1 @ Wmix1 (3N x 512).
    // col 0 -> fused vVn; col 1 -> vW (fp16).
    {
        MP p = {};
        p.Af = l1; p.ldaf = 256; p.ksplit = 256;
        p.Ah = a2h; p.Al = a2l; p.ldah = 512; p.coffh = 0;
        p.B = bt1; p.M = M1; p.K = 256; p.mstep = 126;
        p.vwout = vw; p.Oh = a2h; p.Ol = a2l;
        gemm_mma<0><<<dim3(2, mt1), 512, SMEM_ALL>>>(p);
    }

    // GEMM2 (l0 single-pass, vVn 2-pass): h = silu([l0|vVn] @ W1a + b1a).
    {
        MP p = {};
        p.Af = l0; p.ldaf = 256; p.ksplit = 256;
        p.Ah = a2h; p.Al = a2l; p.ldah = 512; p.coffh = 256;
        p.B = bt2; p.M = natoms; p.K = 512; p.mstep = 128;
        p.Oh = a3h; p.Ol = a3l; p.bias = b1a;
        gemm_mma<1><<<dim3(1, mt), 512, SMEM_ALL>>>(p);
    }

    // GEMM3 (2-pass, 3-stage): col 0: s1 -> a4 hi/lo; col 1: fused stage2a.
    {
        MP p = {};
        p.Af = nullptr; p.ldaf = 256; p.ksplit = 0;
        p.Ah = a3h; p.Al = a3l; p.ldah = 256; p.coffh = 0;
        p.B = bt3; p.M = natoms; p.K = 256; p.mstep = 128;
        p.Oh = a4h; p.Ol = a4l; p.bias = b2a;
        p.vw = vw; p.Wmix2 = Wmix2; p.vvn2 = vvn2; p.vw2 = vw2;
        gemm_mma<2><<<dim3(2, mt), 512, SMEM_ALL>>>(p);
    }

    // GEMM4 (2-pass, 3-stage): h2 -> fused stage2b.
    {
        MP p = {};
        p.Af = nullptr; p.ldaf = 256; p.ksplit = 0;
        p.Ah = a4h; p.Al = a4l; p.ldah = 256; p.coffh = 0;
        p.B = bt4; p.M = natoms; p.K = 256; p.mstep = 128;
        p.bias = b1b; p.u = vvn2; p.vrow = W1b + 256 * 256;
        p.W2b = W2b; p.b2b = b2b; p.pos = pos; p.batch = batch;
        p.vw2 = vw2; p.out = out; p.nmol = nmol;
        gemm_mma<3><<<dim3(1, mt), 512, SMEM_ALL>>>(p);
    }
}